// round 16
// baseline (speedup 1.0000x reference)
#include <cuda_runtime.h>
#include <cuda_fp16.h>
#include <math.h>
#include <stdint.h>

#define DIM 4096
#define BSZ 1024
#define NW  12
#define BK  64                 // halves per tile row = 128B
#define NS  (DIM / BK)         // 64
#define TS  (128 * 128)        // bytes per 128x64 half tile
#define PSTG (2 * TS)          // product-block stage: A, B (32KB)
#define G1_PROD 512            // 256 tiles x 2 products
#define G2_PROD 768            // 256 tiles x 3 products

// ---------------- device-global scratch ----------------
__device__ __align__(16) __half g_Ar[(size_t)DIM * DIM];
__device__ __align__(16) __half g_Ai[(size_t)DIM * DIM];
__device__ __align__(16) __half g_Br[(size_t)DIM * DIM];
__device__ __align__(16) __half g_Bi[(size_t)DIM * DIM];
__device__ __align__(16) __half g_Bp[(size_t)DIM * DIM];
__device__ __align__(16) __half g_x [(size_t)BSZ * DIM];
__device__ __align__(16) __half g_sr[(size_t)BSZ * DIM];
__device__ __align__(16) __half g_si[(size_t)BSZ * DIM];
__device__ __align__(16) __half g_sp[(size_t)BSZ * DIM];
__device__ __align__(16) float  g_T[3][(size_t)BSZ * DIM];  // gemm2 partials
__device__ float g_norm[BSZ];

// ---------------- helpers ----------------
__device__ __forceinline__ uint32_t pkh(float a, float b) {
    __half2 h = __floats2half2_rn(a, b);
    return *(uint32_t*)&h;
}
__device__ __forceinline__ uint2 pk4(float4 v) {
    return make_uint2(pkh(v.x, v.y), pkh(v.z, v.w));
}
__device__ __forceinline__ void cp16(uint32_t dst, const void* src) {
    asm volatile("cp.async.cg.shared.global [%0], [%1], 16;" :: "r"(dst), "l"(src));
}
#define CP_COMMIT() asm volatile("cp.async.commit_group;" ::: "memory")
#define CP_WAIT1()  asm volatile("cp.async.wait_group 1;" ::: "memory")
#define CP_WAIT0()  asm volatile("cp.async.wait_group 0;" ::: "memory")

__device__ __forceinline__ void ldsm4(uint32_t r[4], uint32_t addr) {
    asm volatile("ldmatrix.sync.aligned.m8n8.x4.shared.b16 {%0,%1,%2,%3}, [%4];"
        : "=r"(r[0]), "=r"(r[1]), "=r"(r[2]), "=r"(r[3]) : "r"(addr));
}
__device__ __forceinline__ void mma_f16(float c[4], const uint32_t a[4], const uint32_t b[2]) {
    asm volatile("mma.sync.aligned.m16n8k16.row.col.f32.f16.f16.f32 "
        "{%0,%1,%2,%3},{%4,%5,%6,%7},{%8,%9},{%0,%1,%2,%3};"
        : "+f"(c[0]), "+f"(c[1]), "+f"(c[2]), "+f"(c[3])
        : "r"(a[0]), "r"(a[1]), "r"(a[2]), "r"(a[3]), "r"(b[0]), "r"(b[1]));
}

// 128x64 half tile, 128B rows, XOR-swizzled 16B chunks (ch ^= r&7)
__device__ __forceinline__ void cpah(const __half* __restrict__ src,
                                     int row0, int k0, uint32_t smt, int tid) {
#pragma unroll
    for (int it = 0; it < 4; ++it) {
        int c = tid + it * 256;
        int r = c >> 3, ch = c & 7;
        cp16(smt + r * 128 + ((ch ^ (r & 7)) << 4),
             src + (size_t)(row0 + r) * DIM + k0 + ch * 8);
    }
}

__device__ __forceinline__ int perm_of(int j) {
    int idx = j;
#pragma unroll
    for (int i = NW - 1; i >= 0; --i) {
        int c = i, t = (i + 1) % NW;
        int cb = (idx >> (NW - 1 - c)) & 1;
        idx ^= cb << (NW - 1 - t);
    }
    return idx;   // out_state[j] = in_state[perm_of(j)]
}

// ---------------------------------------------------------------------------
// PREP: blocks [0, DIM): permuted row-gather U -> Ar/Ai
//       blocks [DIM, DIM+BSZ): norm + fp16 convert of x
// ---------------------------------------------------------------------------
__global__ __launch_bounds__(256)
void prep_kernel(const float* __restrict__ Ure, const float* __restrict__ Uim,
                 const float* __restrict__ x) {
    int bid = blockIdx.x;
    int c0 = threadIdx.x;
    if (bid < DIM) {
        int j = bid;
        int src = perm_of(j);
        const float4* pr = (const float4*)(Ure + (size_t)src * DIM);
        const float4* pi = (const float4*)(Uim + (size_t)src * DIM);
        uint2* dr = (uint2*)(g_Ar + (size_t)j * DIM);
        uint2* di = (uint2*)(g_Ai + (size_t)j * DIM);
        float4 v[4], w[4];
#pragma unroll
        for (int it = 0; it < 4; ++it) v[it] = __ldg(&pr[c0 + it * 256]);
#pragma unroll
        for (int it = 0; it < 4; ++it) w[it] = __ldg(&pi[c0 + it * 256]);
#pragma unroll
        for (int it = 0; it < 4; ++it) {
            int c = c0 + it * 256;
            dr[c] = pk4(v[it]);
            di[c] = pk4(w[it]);
        }
        return;
    }
    int b = bid - DIM;
    const float4* xr = (const float4*)(x + (size_t)b * DIM);
    uint2* dh = (uint2*)(g_x + (size_t)b * DIM);
    float4 v[4];
    float s = 0.f;
#pragma unroll
    for (int it = 0; it < 4; ++it) v[it] = __ldg(&xr[c0 + it * 256]);
#pragma unroll
    for (int it = 0; it < 4; ++it) {
        dh[c0 + it * 256] = pk4(v[it]);
        s += v[it].x * v[it].x + v[it].y * v[it].y + v[it].z * v[it].z + v[it].w * v[it].w;
    }
    __shared__ float red[8];
#pragma unroll
    for (int o = 16; o > 0; o >>= 1) s += __shfl_down_sync(0xffffffffu, s, o);
    if ((threadIdx.x & 31) == 0) red[threadIdx.x >> 5] = s;
    __syncthreads();
    if (threadIdx.x == 0) {
        float tot = 0.f;
#pragma unroll
        for (int i = 0; i < 8; ++i) tot += red[i];
        g_norm[b] = sqrtf(tot);
    }
}

// ---------------------------------------------------------------------------
// Shared GEMM mainloop body (product block, 128x128 tile, 8 warps as 4m x 2n,
// warp tile 32m x 64n, ldsm4 on both operands).
// ---------------------------------------------------------------------------
struct FragCtx {
    uint32_t apre[2], axor[2], bpre[4], bxor[4], ahalf, bhalf;
};
__device__ __forceinline__ void frag_init(FragCtx& fc, int lane, int wm0, int wn0) {
#pragma unroll
    for (int mt = 0; mt < 2; ++mt) {
        int r = wm0 + mt * 16 + (lane & 15);
        fc.apre[mt] = r * 128;
        fc.axor[mt] = (r & 7) << 4;
    }
#pragma unroll
    for (int nt2 = 0; nt2 < 4; ++nt2) {
        int r = wn0 + nt2 * 16 + ((lane >> 4) << 3) + (lane & 7);
        fc.bpre[nt2] = r * 128;
        fc.bxor[nt2] = (r & 7) << 4;
    }
    fc.ahalf = (lane >> 4) << 4;
    fc.bhalf = ((lane >> 3) & 1) << 4;
}
__device__ __forceinline__ void gemm_step(float acc[2][8][4], const FragCtx& fc,
                                          uint32_t sb) {
#pragma unroll
    for (int j = 0; j < 4; ++j) {
        const uint32_t ko = j * 32;
        uint32_t av[2][4], bv[4][4];
#pragma unroll
        for (int nt2 = 0; nt2 < 4; ++nt2)
            ldsm4(bv[nt2], sb + 1 * TS + fc.bpre[nt2] + ((ko + fc.bhalf) ^ fc.bxor[nt2]));
#pragma unroll
        for (int mt = 0; mt < 2; ++mt)
            ldsm4(av[mt], sb + 0 * TS + fc.apre[mt] + ((ko + fc.ahalf) ^ fc.axor[mt]));
#pragma unroll
        for (int mt = 0; mt < 2; ++mt)
#pragma unroll
            for (int nt = 0; nt < 8; ++nt)
                mma_f16(acc[mt][nt], av[mt], &bv[nt >> 1][(nt & 1) * 2]);
    }
}

// ---------------------------------------------------------------------------
// GEMM1 product blocks + fused U1 conversion:
//   bid < 512 : tile = bid>>1, p = bid&1. Compute (p? Ai:Ar)·x -> g_si/g_sr
//   bid >= 512: convert U1 row -> Br, Bi, Bp
// ---------------------------------------------------------------------------
__global__ __launch_bounds__(256, 2)
void gemm1_kernel(const float* __restrict__ U1re, const float* __restrict__ U1im) {
    const int tid = threadIdx.x;

    if (blockIdx.x >= G1_PROD) {
        int j = blockIdx.x - G1_PROD;
        const float4* pr = (const float4*)(U1re + (size_t)j * DIM);
        const float4* pi = (const float4*)(U1im + (size_t)j * DIM);
        uint2* dr = (uint2*)(g_Br + (size_t)j * DIM);
        uint2* di = (uint2*)(g_Bi + (size_t)j * DIM);
        uint2* dp = (uint2*)(g_Bp + (size_t)j * DIM);
        float4 v[4], w[4];
#pragma unroll
        for (int it = 0; it < 4; ++it) v[it] = __ldg(&pr[tid + it * 256]);
#pragma unroll
        for (int it = 0; it < 4; ++it) w[it] = __ldg(&pi[tid + it * 256]);
#pragma unroll
        for (int it = 0; it < 4; ++it) {
            int c = tid + it * 256;
            dr[c] = pk4(v[it]);
            di[c] = pk4(w[it]);
            float4 p;
            p.x = v[it].x + w[it].x; p.y = v[it].y + w[it].y;
            p.z = v[it].z + w[it].z; p.w = v[it].w + w[it].w;
            dp[c] = pk4(p);
        }
        return;
    }

    const int tile = blockIdx.x >> 1, p = blockIdx.x & 1;
    const __half* Asrc = p ? g_Ai : g_Ar;
    __half* Dst = p ? g_si : g_sr;

    extern __shared__ char smem[];
    uint32_t sbase = (uint32_t)__cvta_generic_to_shared(smem);
    const int lane = tid & 31, wid = tid >> 5;
    const int g = lane >> 2, tg = lane & 3;
    const int wm0 = (wid >> 1) * 32, wn0 = (wid & 1) * 64;
    const int m0 = (tile >> 3) * 128, n0 = (tile & 7) * 128;

    float acc[2][8][4];
#pragma unroll
    for (int a = 0; a < 2; ++a)
#pragma unroll
        for (int b = 0; b < 8; ++b)
#pragma unroll
            for (int c = 0; c < 4; ++c) acc[a][b][c] = 0.f;

    FragCtx fc;
    frag_init(fc, lane, wm0, wn0);

#define G1_LOAD(st, t) do {                                \
    uint32_t _sb = sbase + (st) * PSTG; int _k0 = (t) * BK; \
    cpah(Asrc, m0, _k0, _sb + 0 * TS, tid);                 \
    cpah(g_x,  n0, _k0, _sb + 1 * TS, tid);                 \
} while (0)

    G1_LOAD(0, 0); CP_COMMIT();
    for (int t = 0; t < NS; ++t) {
        if (t + 1 < NS) { G1_LOAD((t + 1) & 1, t + 1); CP_COMMIT(); CP_WAIT1(); }
        else CP_WAIT0();
        __syncthreads();
        gemm_step(acc, fc, sbase + (t & 1) * PSTG);
        __syncthreads();
    }
#undef G1_LOAD

#pragma unroll
    for (int mt = 0; mt < 2; ++mt)
#pragma unroll
        for (int nt = 0; nt < 8; ++nt)
#pragma unroll
            for (int c = 0; c < 4; ++c) {
                const int m = m0 + wm0 + mt * 16 + g + ((c >> 1) << 3);
                const int b = n0 + wn0 + nt * 8 + tg * 2 + (c & 1);
                Dst[(size_t)b * DIM + m] = __float2half_rn(acc[mt][nt][c]);
            }
}

// sp = sr + si (fp16), vectorized
__global__ __launch_bounds__(256) void sp_kernel() {
    size_t i = (size_t)blockIdx.x * 256 + threadIdx.x;
    const uint2* a = (const uint2*)g_sr;
    const uint2* b = (const uint2*)g_si;
    uint2* d = (uint2*)g_sp;
#pragma unroll
    for (int it = 0; it < 2; ++it) {
        size_t c = i + (size_t)it * gridDim.x * 256;
        uint2 va = a[c], vb = b[c], o;
        asm("add.f16x2 %0, %1, %2;" : "=r"(o.x) : "r"(va.x), "r"(vb.x));
        asm("add.f16x2 %0, %1, %2;" : "=r"(o.y) : "r"(va.y), "r"(vb.y));
        d[c] = o;
    }
}

// ---------------------------------------------------------------------------
// GEMM2 product blocks: bid -> tile = bid/3, p = bid%3.
// T_p = {Br,Bi,Bp}[p] · {sr,si,sp}[p] -> g_T[p] (fp32).
// ---------------------------------------------------------------------------
__global__ __launch_bounds__(256, 2)
void gemm2_kernel() {
    const int tid = threadIdx.x;
    const int tile = blockIdx.x / 3, p = blockIdx.x - tile * 3;
    const __half* Asrc = (p == 0) ? g_Br : (p == 1) ? g_Bi : g_Bp;
    const __half* Bsrc = (p == 0) ? g_sr : (p == 1) ? g_si : g_sp;
    float* Dst = g_T[p];

    extern __shared__ char smem[];
    uint32_t sbase = (uint32_t)__cvta_generic_to_shared(smem);
    const int lane = tid & 31, wid = tid >> 5;
    const int g = lane >> 2, tg = lane & 3;
    const int wm0 = (wid >> 1) * 32, wn0 = (wid & 1) * 64;
    const int m0 = (tile >> 3) * 128, n0 = (tile & 7) * 128;

    float acc[2][8][4];
#pragma unroll
    for (int a = 0; a < 2; ++a)
#pragma unroll
        for (int b = 0; b < 8; ++b)
#pragma unroll
            for (int c = 0; c < 4; ++c) acc[a][b][c] = 0.f;

    FragCtx fc;
    frag_init(fc, lane, wm0, wn0);

#define G2_LOAD(st, t) do {                                \
    uint32_t _sb = sbase + (st) * PSTG; int _k0 = (t) * BK; \
    cpah(Asrc, m0, _k0, _sb + 0 * TS, tid);                 \
    cpah(Bsrc, n0, _k0, _sb + 1 * TS, tid);                 \
} while (0)

    G2_LOAD(0, 0); CP_COMMIT();
    for (int t = 0; t < NS; ++t) {
        if (t + 1 < NS) { G2_LOAD((t + 1) & 1, t + 1); CP_COMMIT(); CP_WAIT1(); }
        else CP_WAIT0();
        __syncthreads();
        gemm_step(acc, fc, sbase + (t & 1) * PSTG);
        __syncthreads();
    }
#undef G2_LOAD

#pragma unroll
    for (int mt = 0; mt < 2; ++mt)
#pragma unroll
        for (int nt = 0; nt < 8; ++nt)
#pragma unroll
            for (int c = 0; c < 4; ++c) {
                const int i = m0 + wm0 + mt * 16 + g + ((c >> 1) << 3);
                const int b = n0 + wn0 + nt * 8 + tg * 2 + (c & 1);
                Dst[(size_t)b * DIM + i] = acc[mt][nt][c];
            }
}

// combine: re=T1-T2, im=T3-T1-T2 ; out = sqrt(re^2+im^2)/norm[b]
__global__ __launch_bounds__(256) void epi_kernel(float* __restrict__ out) {
    const int b = blockIdx.x >> 2;
    const size_t base = ((size_t)b << 12) + ((blockIdx.x & 3) << 10) + threadIdx.x * 4;
    const float inv = 1.0f / g_norm[b];
    float4 t1 = *(const float4*)&g_T[0][base];
    float4 t2 = *(const float4*)&g_T[1][base];
    float4 t3 = *(const float4*)&g_T[2][base];
    float4 o;
    { float re = t1.x - t2.x, im = t3.x - t1.x - t2.x; o.x = sqrtf(re * re + im * im) * inv; }
    { float re = t1.y - t2.y, im = t3.y - t1.y - t2.y; o.y = sqrtf(re * re + im * im) * inv; }
    { float re = t1.z - t2.z, im = t3.z - t1.z - t2.z; o.z = sqrtf(re * re + im * im) * inv; }
    { float re = t1.w - t2.w, im = t3.w - t1.w - t2.w; o.w = sqrtf(re * re + im * im) * inv; }
    *(float4*)&out[base] = o;
}

// ---------------------------------------------------------------------------
extern "C" void kernel_launch(void* const* d_in, const int* in_sizes, int n_in,
                              void* d_out, int out_size) {
    const float* x     = (const float*)d_in[0];
    const float* U_re  = (const float*)d_in[1];
    const float* U_im  = (const float*)d_in[2];
    const float* U1_re = (const float*)d_in[3];
    const float* U1_im = (const float*)d_in[4];
    float* out = (float*)d_out;

    cudaFuncSetAttribute(gemm1_kernel, cudaFuncAttributeMaxDynamicSharedMemorySize, 2 * PSTG);
    cudaFuncSetAttribute(gemm2_kernel, cudaFuncAttributeMaxDynamicSharedMemorySize, 2 * PSTG);

    prep_kernel<<<DIM + BSZ, 256>>>(U_re, U_im, x);
    gemm1_kernel<<<G1_PROD + DIM, 256, 2 * PSTG>>>(U1_re, U1_im);
    sp_kernel<<<2048, 256>>>();
    gemm2_kernel<<<G2_PROD, 256, 2 * PSTG>>>();
    epi_kernel<<<BSZ * 4, 256>>>(out);
}

// round 17
// speedup vs baseline: 1.0297x; 1.0297x over previous
#include <cuda_runtime.h>
#include <cuda_fp16.h>
#include <math.h>
#include <stdint.h>

#define DIM 4096
#define BSZ 1024
#define NW  12
#define BK  64                 // halves per tile row = 128B
#define NS  (DIM / BK)         // 64
#define TS  (128 * 128)        // bytes per 128x64 half tile
#define PSTG (2 * TS)          // product-block stage: A, B (32KB)
#define G1_PROD 512            // 256 tiles x 2 products
#define G2_PROD 768            // 256 tiles x 3 products
#define GT 128                 // gemm block threads

// ---------------- device-global scratch ----------------
__device__ __align__(16) __half g_Ar[(size_t)DIM * DIM];
__device__ __align__(16) __half g_Ai[(size_t)DIM * DIM];
__device__ __align__(16) __half g_Br[(size_t)DIM * DIM];
__device__ __align__(16) __half g_Bi[(size_t)DIM * DIM];
__device__ __align__(16) __half g_Bp[(size_t)DIM * DIM];
__device__ __align__(16) __half g_x [(size_t)BSZ * DIM];
__device__ __align__(16) __half g_sr[(size_t)BSZ * DIM];
__device__ __align__(16) __half g_si[(size_t)BSZ * DIM];
__device__ __align__(16) __half g_sp[(size_t)BSZ * DIM];
__device__ __align__(16) float  g_T[3][(size_t)BSZ * DIM];  // gemm2 partials
__device__ float g_norm[BSZ];

// ---------------- helpers ----------------
__device__ __forceinline__ uint32_t pkh(float a, float b) {
    __half2 h = __floats2half2_rn(a, b);
    return *(uint32_t*)&h;
}
__device__ __forceinline__ uint2 pk4(float4 v) {
    return make_uint2(pkh(v.x, v.y), pkh(v.z, v.w));
}
__device__ __forceinline__ void cp16(uint32_t dst, const void* src) {
    asm volatile("cp.async.cg.shared.global [%0], [%1], 16;" :: "r"(dst), "l"(src));
}
#define CP_COMMIT() asm volatile("cp.async.commit_group;" ::: "memory")
#define CP_WAIT1()  asm volatile("cp.async.wait_group 1;" ::: "memory")
#define CP_WAIT0()  asm volatile("cp.async.wait_group 0;" ::: "memory")

__device__ __forceinline__ void ldsm4(uint32_t r[4], uint32_t addr) {
    asm volatile("ldmatrix.sync.aligned.m8n8.x4.shared.b16 {%0,%1,%2,%3}, [%4];"
        : "=r"(r[0]), "=r"(r[1]), "=r"(r[2]), "=r"(r[3]) : "r"(addr));
}
__device__ __forceinline__ void mma_f16(float c[4], const uint32_t a[4], const uint32_t b[2]) {
    asm volatile("mma.sync.aligned.m16n8k16.row.col.f32.f16.f16.f32 "
        "{%0,%1,%2,%3},{%4,%5,%6,%7},{%8,%9},{%0,%1,%2,%3};"
        : "+f"(c[0]), "+f"(c[1]), "+f"(c[2]), "+f"(c[3])
        : "r"(a[0]), "r"(a[1]), "r"(a[2]), "r"(a[3]), "r"(b[0]), "r"(b[1]));
}

// 128x64 half tile, 128B rows, XOR-swizzled 16B chunks (ch ^= r&7)
template <int THREADS>
__device__ __forceinline__ void cpah(const __half* __restrict__ src,
                                     int row0, int k0, uint32_t smt, int tid) {
#pragma unroll
    for (int it = 0; it < 1024 / THREADS; ++it) {
        int c = tid + it * THREADS;
        int r = c >> 3, ch = c & 7;
        cp16(smt + r * 128 + ((ch ^ (r & 7)) << 4),
             src + (size_t)(row0 + r) * DIM + k0 + ch * 8);
    }
}

__device__ __forceinline__ int perm_of(int j) {
    int idx = j;
#pragma unroll
    for (int i = NW - 1; i >= 0; --i) {
        int c = i, t = (i + 1) % NW;
        int cb = (idx >> (NW - 1 - c)) & 1;
        idx ^= cb << (NW - 1 - t);
    }
    return idx;   // out_state[j] = in_state[perm_of(j)]
}

// ---------------------------------------------------------------------------
// PREP: blocks [0, DIM): permuted row-gather U -> Ar/Ai
//       blocks [DIM, DIM+BSZ): norm + fp16 convert of x
// ---------------------------------------------------------------------------
__global__ __launch_bounds__(256)
void prep_kernel(const float* __restrict__ Ure, const float* __restrict__ Uim,
                 const float* __restrict__ x) {
    int bid = blockIdx.x;
    int c0 = threadIdx.x;
    if (bid < DIM) {
        int j = bid;
        int src = perm_of(j);
        const float4* pr = (const float4*)(Ure + (size_t)src * DIM);
        const float4* pi = (const float4*)(Uim + (size_t)src * DIM);
        uint2* dr = (uint2*)(g_Ar + (size_t)j * DIM);
        uint2* di = (uint2*)(g_Ai + (size_t)j * DIM);
        float4 v[4], w[4];
#pragma unroll
        for (int it = 0; it < 4; ++it) v[it] = __ldg(&pr[c0 + it * 256]);
#pragma unroll
        for (int it = 0; it < 4; ++it) w[it] = __ldg(&pi[c0 + it * 256]);
#pragma unroll
        for (int it = 0; it < 4; ++it) {
            int c = c0 + it * 256;
            dr[c] = pk4(v[it]);
            di[c] = pk4(w[it]);
        }
        return;
    }
    int b = bid - DIM;
    const float4* xr = (const float4*)(x + (size_t)b * DIM);
    uint2* dh = (uint2*)(g_x + (size_t)b * DIM);
    float4 v[4];
    float s = 0.f;
#pragma unroll
    for (int it = 0; it < 4; ++it) v[it] = __ldg(&xr[c0 + it * 256]);
#pragma unroll
    for (int it = 0; it < 4; ++it) {
        dh[c0 + it * 256] = pk4(v[it]);
        s += v[it].x * v[it].x + v[it].y * v[it].y + v[it].z * v[it].z + v[it].w * v[it].w;
    }
    __shared__ float red[8];
#pragma unroll
    for (int o = 16; o > 0; o >>= 1) s += __shfl_down_sync(0xffffffffu, s, o);
    if ((threadIdx.x & 31) == 0) red[threadIdx.x >> 5] = s;
    __syncthreads();
    if (threadIdx.x == 0) {
        float tot = 0.f;
#pragma unroll
        for (int i = 0; i < 8; ++i) tot += red[i];
        g_norm[b] = sqrtf(tot);
    }
}

// ---------------------------------------------------------------------------
// Product-GEMM mainloop: 128x128 tile, 4 warps (2m x 2n), warp tile 64x64.
// Per j-step per warp: 4 ldsm4 (A) + 4 ldsm4 (B) -> 32 MMA.
// ---------------------------------------------------------------------------
struct FragCtx {
    uint32_t apre[4], axor[4], bpre[4], bxor[4], ahalf, bhalf;
};
__device__ __forceinline__ void frag_init(FragCtx& fc, int lane, int wm0, int wn0) {
#pragma unroll
    for (int mt = 0; mt < 4; ++mt) {
        int r = wm0 + mt * 16 + (lane & 15);
        fc.apre[mt] = r * 128;
        fc.axor[mt] = (r & 7) << 4;
    }
#pragma unroll
    for (int nt2 = 0; nt2 < 4; ++nt2) {
        int r = wn0 + nt2 * 16 + ((lane >> 4) << 3) + (lane & 7);
        fc.bpre[nt2] = r * 128;
        fc.bxor[nt2] = (r & 7) << 4;
    }
    fc.ahalf = (lane >> 4) << 4;
    fc.bhalf = ((lane >> 3) & 1) << 4;
}
__device__ __forceinline__ void gemm_step(float acc[4][8][4], const FragCtx& fc,
                                          uint32_t sb) {
#pragma unroll
    for (int j = 0; j < 4; ++j) {
        const uint32_t ko = j * 32;
        uint32_t av[4][4], bv[4][4];
#pragma unroll
        for (int nt2 = 0; nt2 < 4; ++nt2)
            ldsm4(bv[nt2], sb + 1 * TS + fc.bpre[nt2] + ((ko + fc.bhalf) ^ fc.bxor[nt2]));
#pragma unroll
        for (int mt = 0; mt < 4; ++mt)
            ldsm4(av[mt], sb + 0 * TS + fc.apre[mt] + ((ko + fc.ahalf) ^ fc.axor[mt]));
#pragma unroll
        for (int mt = 0; mt < 4; ++mt)
#pragma unroll
            for (int nt = 0; nt < 8; ++nt)
                mma_f16(acc[mt][nt], av[mt], &bv[nt >> 1][(nt & 1) * 2]);
    }
}

// ---------------------------------------------------------------------------
// GEMM1 product blocks + fused U1 conversion:
//   bid < 512 : tile = bid>>1, p = bid&1. Compute (p? Ai:Ar)·x -> g_si/g_sr
//   bid >= 512: convert U1 row -> Br, Bi, Bp (128 threads)
// ---------------------------------------------------------------------------
__global__ __launch_bounds__(GT, 2)
void gemm1_kernel(const float* __restrict__ U1re, const float* __restrict__ U1im) {
    const int tid = threadIdx.x;

    if (blockIdx.x >= G1_PROD) {
        int j = blockIdx.x - G1_PROD;
        const float4* pr = (const float4*)(U1re + (size_t)j * DIM);
        const float4* pi = (const float4*)(U1im + (size_t)j * DIM);
        uint2* dr = (uint2*)(g_Br + (size_t)j * DIM);
        uint2* di = (uint2*)(g_Bi + (size_t)j * DIM);
        uint2* dp = (uint2*)(g_Bp + (size_t)j * DIM);
#pragma unroll
        for (int it = 0; it < 8; ++it) {
            int c = tid + it * GT;
            float4 v = __ldg(&pr[c]);
            float4 w = __ldg(&pi[c]);
            dr[c] = pk4(v);
            di[c] = pk4(w);
            float4 p;
            p.x = v.x + w.x; p.y = v.y + w.y;
            p.z = v.z + w.z; p.w = v.w + w.w;
            dp[c] = pk4(p);
        }
        return;
    }

    const int tile = blockIdx.x >> 1, p = blockIdx.x & 1;
    const __half* Asrc = p ? g_Ai : g_Ar;
    __half* Dst = p ? g_si : g_sr;

    extern __shared__ char smem[];
    uint32_t sbase = (uint32_t)__cvta_generic_to_shared(smem);
    const int lane = tid & 31, wid = tid >> 5;
    const int g = lane >> 2, tg = lane & 3;
    const int wm0 = (wid >> 1) * 64, wn0 = (wid & 1) * 64;
    const int m0 = (tile >> 3) * 128, n0 = (tile & 7) * 128;

    float acc[4][8][4];
#pragma unroll
    for (int a = 0; a < 4; ++a)
#pragma unroll
        for (int b = 0; b < 8; ++b)
#pragma unroll
            for (int c = 0; c < 4; ++c) acc[a][b][c] = 0.f;

    FragCtx fc;
    frag_init(fc, lane, wm0, wn0);

#define G1_LOAD(st, t) do {                                \
    uint32_t _sb = sbase + (st) * PSTG; int _k0 = (t) * BK; \
    cpah<GT>(Asrc, m0, _k0, _sb + 0 * TS, tid);             \
    cpah<GT>(g_x,  n0, _k0, _sb + 1 * TS, tid);             \
} while (0)

    G1_LOAD(0, 0); CP_COMMIT();
    for (int t = 0; t < NS; ++t) {
        if (t + 1 < NS) { G1_LOAD((t + 1) & 1, t + 1); CP_COMMIT(); CP_WAIT1(); }
        else CP_WAIT0();
        __syncthreads();
        gemm_step(acc, fc, sbase + (t & 1) * PSTG);
        __syncthreads();
    }
#undef G1_LOAD

#pragma unroll
    for (int mt = 0; mt < 4; ++mt)
#pragma unroll
        for (int nt = 0; nt < 8; ++nt)
#pragma unroll
            for (int c = 0; c < 4; ++c) {
                const int m = m0 + wm0 + mt * 16 + g + ((c >> 1) << 3);
                const int b = n0 + wn0 + nt * 8 + tg * 2 + (c & 1);
                Dst[(size_t)b * DIM + m] = __float2half_rn(acc[mt][nt][c]);
            }
}

// sp = sr + si (fp16), vectorized
__global__ __launch_bounds__(256) void sp_kernel() {
    size_t i = (size_t)blockIdx.x * 256 + threadIdx.x;
    const uint2* a = (const uint2*)g_sr;
    const uint2* b = (const uint2*)g_si;
    uint2* d = (uint2*)g_sp;
#pragma unroll
    for (int it = 0; it < 2; ++it) {
        size_t c = i + (size_t)it * gridDim.x * 256;
        uint2 va = a[c], vb = b[c], o;
        asm("add.f16x2 %0, %1, %2;" : "=r"(o.x) : "r"(va.x), "r"(vb.x));
        asm("add.f16x2 %0, %1, %2;" : "=r"(o.y) : "r"(va.y), "r"(vb.y));
        d[c] = o;
    }
}

// ---------------------------------------------------------------------------
// GEMM2 product blocks: bid -> tile = bid/3, p = bid%3.
// T_p = {Br,Bi,Bp}[p] · {sr,si,sp}[p] -> g_T[p] (fp32).
// ---------------------------------------------------------------------------
__global__ __launch_bounds__(GT, 2)
void gemm2_kernel() {
    const int tid = threadIdx.x;
    const int tile = blockIdx.x / 3, p = blockIdx.x - tile * 3;
    const __half* Asrc = (p == 0) ? g_Br : (p == 1) ? g_Bi : g_Bp;
    const __half* Bsrc = (p == 0) ? g_sr : (p == 1) ? g_si : g_sp;
    float* Dst = g_T[p];

    extern __shared__ char smem[];
    uint32_t sbase = (uint32_t)__cvta_generic_to_shared(smem);
    const int lane = tid & 31, wid = tid >> 5;
    const int g = lane >> 2, tg = lane & 3;
    const int wm0 = (wid >> 1) * 64, wn0 = (wid & 1) * 64;
    const int m0 = (tile >> 3) * 128, n0 = (tile & 7) * 128;

    float acc[4][8][4];
#pragma unroll
    for (int a = 0; a < 4; ++a)
#pragma unroll
        for (int b = 0; b < 8; ++b)
#pragma unroll
            for (int c = 0; c < 4; ++c) acc[a][b][c] = 0.f;

    FragCtx fc;
    frag_init(fc, lane, wm0, wn0);

#define G2_LOAD(st, t) do {                                \
    uint32_t _sb = sbase + (st) * PSTG; int _k0 = (t) * BK; \
    cpah<GT>(Asrc, m0, _k0, _sb + 0 * TS, tid);             \
    cpah<GT>(Bsrc, n0, _k0, _sb + 1 * TS, tid);             \
} while (0)

    G2_LOAD(0, 0); CP_COMMIT();
    for (int t = 0; t < NS; ++t) {
        if (t + 1 < NS) { G2_LOAD((t + 1) & 1, t + 1); CP_COMMIT(); CP_WAIT1(); }
        else CP_WAIT0();
        __syncthreads();
        gemm_step(acc, fc, sbase + (t & 1) * PSTG);
        __syncthreads();
    }
#undef G2_LOAD

#pragma unroll
    for (int mt = 0; mt < 4; ++mt)
#pragma unroll
        for (int nt = 0; nt < 8; ++nt)
#pragma unroll
            for (int c = 0; c < 4; ++c) {
                const int i = m0 + wm0 + mt * 16 + g + ((c >> 1) << 3);
                const int b = n0 + wn0 + nt * 8 + tg * 2 + (c & 1);
                Dst[(size_t)b * DIM + i] = acc[mt][nt][c];
            }
}

// combine: re=T1-T2, im=T3-T1-T2 ; out = sqrt(re^2+im^2)/norm[b]
__global__ __launch_bounds__(256) void epi_kernel(float* __restrict__ out) {
    const int b = blockIdx.x >> 2;
    const size_t base = ((size_t)b << 12) + ((blockIdx.x & 3) << 10) + threadIdx.x * 4;
    const float inv = 1.0f / g_norm[b];
    float4 t1 = *(const float4*)&g_T[0][base];
    float4 t2 = *(const float4*)&g_T[1][base];
    float4 t3 = *(const float4*)&g_T[2][base];
    float4 o;
    { float re = t1.x - t2.x, im = t3.x - t1.x - t2.x; o.x = sqrtf(re * re + im * im) * inv; }
    { float re = t1.y - t2.y, im = t3.y - t1.y - t2.y; o.y = sqrtf(re * re + im * im) * inv; }
    { float re = t1.z - t2.z, im = t3.z - t1.z - t2.z; o.z = sqrtf(re * re + im * im) * inv; }
    { float re = t1.w - t2.w, im = t3.w - t1.w - t2.w; o.w = sqrtf(re * re + im * im) * inv; }
    *(float4*)&out[base] = o;
}

// ---------------------------------------------------------------------------
extern "C" void kernel_launch(void* const* d_in, const int* in_sizes, int n_in,
                              void* d_out, int out_size) {
    const float* x     = (const float*)d_in[0];
    const float* U_re  = (const float*)d_in[1];
    const float* U_im  = (const float*)d_in[2];
    const float* U1_re = (const float*)d_in[3];
    const float* U1_im = (const float*)d_in[4];
    float* out = (float*)d_out;

    cudaFuncSetAttribute(gemm1_kernel, cudaFuncAttributeMaxDynamicSharedMemorySize, 2 * PSTG);
    cudaFuncSetAttribute(gemm2_kernel, cudaFuncAttributeMaxDynamicSharedMemorySize, 2 * PSTG);

    prep_kernel<<<DIM + BSZ, 256>>>(U_re, U_im, x);
    gemm1_kernel<<<G1_PROD + DIM, GT, 2 * PSTG>>>(U1_re, U1_im);
    sp_kernel<<<2048, 256>>>();
    gemm2_kernel<<<G2_PROD, GT, 2 * PSTG>>>();
    epi_kernel<<<BSZ * 4, 256>>>(out);
}